// round 15
// baseline (speedup 1.0000x reference)
#include <cuda_runtime.h>
#include <cstdint>

#define F_DIM 16384
#define N_BINS 128
#define NT 256
#define N_ROWS 4096
#define N_OUT 64
#define GRID_P (152 * 3)      // persistent: 3 CTAs/SM x 152 SMs (GB300)
#define NW 8                  // warps per CTA

// Dynamic smem layout (bytes)
#define SM_HIST  0            // 8 warps * 8192 (two 4 KB sub-hists) = 65536
#define SM_RED   65536        // 16 floats  = 64
#define SM_PCNT  65600        // 8 warps * 33 uint4 = 4224
#define SM_CNT   69824        // 128 floats = 512
#define SM_PART  70336        // 256 floats = 1024
#define SM_TOTAL 71360        // x3 CTAs = 209 KB <= 228 KB/SM

// Prep outputs (allocation-free static scratch)
__device__ float g_wt[N_BINS * N_OUT];   // W[:, :128] transposed to [bin][out]
__device__ float g_s0[N_OUT];            // sum_j W[o][128+j]
__device__ float g_s1[N_OUT];            // sum_j (j/128) W[o][128+j]

__device__ __forceinline__ float f_inf() { return __int_as_float(0x7f800000); }

// ---------------------------------------------------------------------------
// Prep: one CTA per output o. Transpose counts-half of W to bin-major and
// reduce the 129 boundary weights to S0/S1.
// ---------------------------------------------------------------------------
__global__ __launch_bounds__(128) void prep_kernel(const float* __restrict__ W) {
    __shared__ float sp0[4], sp1[4];
    const int o = blockIdx.x;
    const int tid = threadIdx.x;

    g_wt[tid * N_OUT + o] = W[o * 257 + tid];

    float wv = W[o * 257 + 128 + tid];
    float s0 = wv;
    float s1 = (float)tid * 0.0078125f * wv;     // exact j/128
    if (tid == 0) {
        float w128 = W[o * 257 + 256];
        s0 += w128;
        s1 += w128;                               // t(128) = 1.0
    }
#pragma unroll
    for (int off = 16; off > 0; off >>= 1) {
        s0 += __shfl_xor_sync(0xFFFFFFFFu, s0, off);
        s1 += __shfl_xor_sync(0xFFFFFFFFu, s1, off);
    }
    if ((tid & 31) == 0) { sp0[tid >> 5] = s0; sp1[tid >> 5] = s1; }
    __syncthreads();
    if (tid == 0) {
        g_s0[o] = sp0[0] + sp0[1] + sp0[2] + sp0[3];
        g_s1[o] = sp1[0] + sp1[1] + sp1[2] + sp1[3];
    }
}

// ---------------------------------------------------------------------------
// Persistent fused kernel — R12 skeleton (NT=256, 3 CTAs/SM, full-register
// rows, prefetch into freed regs) + TWO sub-histograms per lane:
//   values x,z -> hist A, y,w -> hist B. A and B never alias, so all four
//   RMW loads issue before all stores (e02/e13 merge the only intra-hist
//   pairs) -> the serial LDS chain per row halves (32 -> 16 rounds).
// Bank-invariant layout: counter (w, h, b, l) at byte
//   w*8192 + h*4096 + (b>>2)*128 + l*4 + (b&3) -> word bank = l, ANY bin.
// ---------------------------------------------------------------------------
__global__ __launch_bounds__(NT, 3) void hist_kernel(const float* __restrict__ x,
                                                     const float* __restrict__ bias,
                                                     float* __restrict__ out) {
    extern __shared__ unsigned char smem[];
    unsigned char* s_hist = smem + SM_HIST;
    float* s_red = (float*)(smem + SM_RED);
    uint4* s_pcnt4 = (uint4*)(smem + SM_PCNT);
    float* s_cnt = (float*)(smem + SM_CNT);
    float* s_part = (float*)(smem + SM_PART);

    const int tid = threadIdx.x;
    const int w = tid >> 5;
    const int l = tid & 31;
    int row = blockIdx.x;

    // ---- Prologue: load first row into registers ----
    float4 rv[16];
    {
        const float4* __restrict__ xr = (const float4*)(x + (size_t)row * F_DIM);
#pragma unroll
        for (int i = 0; i < 16; i++) rv[i] = __ldcs(xr + tid + i * NT);
    }

    for (;;) {
        const int next = row + GRID_P;
        const bool has_next = (next < N_ROWS);
        const float4* __restrict__ nxt =
            (const float4*)(x + (size_t)(has_next ? next : row) * F_DIM);

        // ---- Warp min/max partial ----
        float mn = f_inf(), mx = -f_inf();
#pragma unroll
        for (int i = 0; i < 16; i++) {
            mn = fminf(mn, fminf(fminf(rv[i].x, rv[i].y), fminf(rv[i].z, rv[i].w)));
            mx = fmaxf(mx, fmaxf(fmaxf(rv[i].x, rv[i].y), fmaxf(rv[i].z, rv[i].w)));
        }
#pragma unroll
        for (int o = 16; o > 0; o >>= 1) {
            mn = fminf(mn, __shfl_xor_sync(0xFFFFFFFFu, mn, o));
            mx = fmaxf(mx, __shfl_xor_sync(0xFFFFFFFFu, mx, o));
        }
        if (l == 0) { s_red[w] = mn; s_red[NW + w] = mx; }
        __syncthreads();                               // JOIN A
        {
            float a = s_red[l & 7];
            float b = s_red[NW + (l & 7)];
#pragma unroll
            for (int o = 4; o > 0; o >>= 1) {
                a = fminf(a, __shfl_xor_sync(0xFFFFFFFFu, a, o));
                b = fmaxf(b, __shfl_xor_sync(0xFFFFFFFFu, b, o));
            }
            mn = a; mx = b;
        }
        const float width = mx - mn;
        const float scale = 128.0f / (width == 0.0f ? 1.0f : width);  // matches jnp where()
        const float nb = -mn * scale;

        // ---- Zero both sub-hists: 16 STS.128, lanes spread across banks ----
        {
            uint4* hz = (uint4*)(s_hist + (w << 13));
            uint4 z = make_uint4(0u, 0u, 0u, 0u);
#pragma unroll
            for (int k = 0; k < 16; k++) hz[k * 32 + l] = z;
        }
        __syncwarp();

        // ---- Bin 64 values: x,z -> hist A; y,w -> hist B. All 4 loads
        // before all 4 stores (A/B disjoint; e02/e13 merge intra-hist pairs)
        // -> 1 RMW round per group, 16 serial rounds per row.
        unsigned char* hA = s_hist + (w << 13) + (l << 2);
        unsigned char* hB = hA + 4096;
#pragma unroll
        for (int i = 0; i < 16; i++) {
            const float4 v = rv[i];
            if (has_next) rv[i] = __ldcs(nxt + tid + i * NT);   // prefetch
            const int b0 = (int)fminf(fmaf(v.x, scale, nb), 127.0f);
            const int b1 = (int)fminf(fmaf(v.y, scale, nb), 127.0f);
            const int b2 = (int)fminf(fmaf(v.z, scale, nb), 127.0f);
            const int b3 = (int)fminf(fmaf(v.w, scale, nb), 127.0f);
            // byte offset: (b>>2)*128 + (b&3) = ((b & 124) << 5) + (b & 3)
            const int o0 = ((b0 & 124) << 5) + (b0 & 3);
            const int o1 = ((b1 & 124) << 5) + (b1 & 3);
            const int o2 = ((b2 & 124) << 5) + (b2 & 3);
            const int o3 = ((b3 & 124) << 5) + (b3 & 3);
            const unsigned int e02 = (b2 == b0) ? 1u : 0u;
            const unsigned int e13 = (b3 == b1) ? 1u : 0u;
            unsigned int c0 = hA[o0];
            unsigned int c2 = hA[o2];
            unsigned int c1 = hB[o1];
            unsigned int c3 = hB[o3];
            hA[o0] = (unsigned char)(c0 + 1u + e02);
            if (!e02) hA[o2] = (unsigned char)(c2 + 1u);
            hB[o1] = (unsigned char)(c1 + 1u + e13);
            if (!e13) hB[o3] = (unsigned char)(c3 + 1u);
        }
        __syncwarp();

        // ---- Warp-local reduce over BOTH sub-hists: lane l owns bins
        // 4l..4l+3; rotated reads (bank (j+l)&31, CF). Packed u16 fields:
        // max 64 words * 32 = 2048 < 65536.
        {
            const unsigned int* h32 = (const unsigned int*)(s_hist + (w << 13));
            unsigned int lo = 0u, hi = 0u;
#pragma unroll
            for (int j = 0; j < 32; j++) {
                const unsigned int vA = h32[(l << 5) + ((j + l) & 31)];
                lo += vA & 0x00FF00FFu;
                hi += (vA >> 8) & 0x00FF00FFu;
            }
#pragma unroll
            for (int j = 0; j < 32; j++) {
                const unsigned int vB = h32[1024 + (l << 5) + ((j + l) & 31)];
                lo += vB & 0x00FF00FFu;
                hi += (vB >> 8) & 0x00FF00FFu;
            }
            s_pcnt4[w * 33 + l] = make_uint4(lo & 0xFFFFu, hi & 0xFFFFu,
                                             lo >> 16, hi >> 16);  // STS.128
        }
        __syncthreads();                               // JOIN B

        // ---- Combine 8 warps' partials: word (w2, b) = w2*132 + b (CF) ----
        if (tid < N_BINS) {
            const unsigned int* p32 = (const unsigned int*)s_pcnt4;
            int s = 0;
#pragma unroll
            for (int w2 = 0; w2 < NW; w2++) s += (int)p32[w2 * 132 + tid];
            s_cnt[tid] = (float)s;
        }
        __syncthreads();                               // JOIN B2

        // ---- Epilogue: out[row][o] = cnt.Wt/F + mn*S0 + wd*S1 + b ----
        {
            const int o = tid & 63;
            const int q = tid >> 6;                    // 4 chunks of 32 bins
            const float* wt = g_wt + (q * 32) * N_OUT + o;
            float acc = 0.0f;
#pragma unroll
            for (int j = 0; j < 32; j++)
                acc = fmaf(s_cnt[q * 32 + j], __ldg(wt + j * N_OUT), acc);
            s_part[tid] = acc;
        }
        __syncthreads();                               // JOIN C
        if (tid < 64) {
            const float bo = bias[tid];
            float s = (s_part[tid] + s_part[tid + 64]) +
                      (s_part[tid + 128] + s_part[tid + 192]);
            float res = fmaf(s, 1.0f / 16384.0f,
                             fmaf(mn, g_s0[tid], fmaf(width, g_s1[tid], bo)));
            out[(size_t)row * N_OUT + tid] = res;
        }

        if (!has_next) break;
        row = next;
    }
}

// ---------------------------------------------------------------------------
extern "C" void kernel_launch(void* const* d_in, const int* in_sizes, int n_in,
                              void* d_out, int out_size) {
    const float* x = (const float*)d_in[0];
    const float* W = (const float*)d_in[1];
    const float* b = (const float*)d_in[2];
    float* out = (float*)d_out;

    cudaFuncSetAttribute(hist_kernel, cudaFuncAttributeMaxDynamicSharedMemorySize,
                         SM_TOTAL);

    prep_kernel<<<N_OUT, 128>>>(W);
    hist_kernel<<<GRID_P, NT, SM_TOTAL>>>(x, b, out);
}

// round 16
// speedup vs baseline: 1.5088x; 1.5088x over previous
#include <cuda_runtime.h>
#include <cstdint>

#define F_DIM 16384
#define N_BINS 128
#define NT 256
#define N_ROWS 4096
#define N_OUT 64
#define GRID_P (152 * 3)      // persistent grid: 3 CTAs/SM on GB300 (152 SMs)
#define NW 8                  // warps per CTA

// Prep outputs (allocation-free static scratch)
__device__ float g_wt[N_BINS * N_OUT];   // W[:, :128] transposed to [bin][out]
__device__ float g_s0[N_OUT];            // sum_j W[o][128+j]
__device__ float g_s1[N_OUT];            // sum_j (j/128) W[o][128+j]

__device__ __forceinline__ float f_inf() { return __int_as_float(0x7f800000); }

// ---------------------------------------------------------------------------
// Prep: one CTA per output o. Transpose counts-half of W to bin-major and
// reduce the 129 boundary weights to S0/S1.
// ---------------------------------------------------------------------------
__global__ __launch_bounds__(128) void prep_kernel(const float* __restrict__ W) {
    __shared__ float sp0[4], sp1[4];
    const int o = blockIdx.x;
    const int tid = threadIdx.x;

    g_wt[tid * N_OUT + o] = W[o * 257 + tid];

    float wv = W[o * 257 + 128 + tid];
    float s0 = wv;
    float s1 = (float)tid * 0.0078125f * wv;     // exact j/128
    if (tid == 0) {
        float w128 = W[o * 257 + 256];
        s0 += w128;
        s1 += w128;                               // t(128) = 1.0
    }
#pragma unroll
    for (int off = 16; off > 0; off >>= 1) {
        s0 += __shfl_xor_sync(0xFFFFFFFFu, s0, off);
        s1 += __shfl_xor_sync(0xFFFFFFFFu, s1, off);
    }
    if ((tid & 31) == 0) { sp0[tid >> 5] = s0; sp1[tid >> 5] = s1; }
    __syncthreads();
    if (tid == 0) {
        g_s0[o] = sp0[0] + sp0[1] + sp0[2] + sp0[3];
        g_s1[o] = sp1[0] + sp1[1] + sp1[2] + sp1[3];
    }
}

// ---------------------------------------------------------------------------
// Persistent fused kernel — the R12 winner (NT=256, 3 CTAs/SM, full-register
// rows, bank-invariant warp-private u8 histograms) with two changes:
//  1. The 16 next-row prefetch LDGs are issued in a burst AFTER the bin loop
//     (they used to ride inside it): the L1-saturated bin phase loses its
//     512 LDG wavefronts, and the DRAM transfers now cover the reduce/
//     combine/epilogue tail where DRAM used to sit idle.
//  2. Epilogue reads s_cnt as float4 broadcast (8 LDS.128 vs 32 LDS.32).
// Hist layout: counter (w, b, l) at byte w*4096 + (b>>2)*128 + l*4 + (b&3)
//   -> word bank = l for ANY bin (conflict-free byte RMW).
// smem ~39 KB x 3 = 117 KB/SM -> g_wt (32 KB) stays L1D-resident.
// ---------------------------------------------------------------------------
__global__ __launch_bounds__(NT, 3) void hist_kernel(const float* __restrict__ x,
                                                     const float* __restrict__ bias,
                                                     float* __restrict__ out) {
    __shared__ unsigned char s_hist[8 * 4096];      // 32768 B
    __shared__ float s_red[16];
    __shared__ int   s_pcnt[N_BINS * 9];            // stride 9: CF combine
    __shared__ alignas(16) float s_cnt[N_BINS];
    __shared__ float s_part[NT];

    const int tid = threadIdx.x;
    const int w = tid >> 5;
    const int l = tid & 31;
    int row = blockIdx.x;

    // ---- Prologue: load first row into registers ----
    float4 rv[16];
    {
        const float4* __restrict__ xr = (const float4*)(x + (size_t)row * F_DIM);
#pragma unroll
        for (int i = 0; i < 16; i++) rv[i] = __ldcs(xr + tid + i * NT);
    }

    for (;;) {
        const int next = row + GRID_P;
        const bool has_next = (next < N_ROWS);
        const float4* __restrict__ nxt =
            (const float4*)(x + (size_t)(has_next ? next : row) * F_DIM);

        // ---- Warp min/max partial ----
        float mn = f_inf(), mx = -f_inf();
#pragma unroll
        for (int i = 0; i < 16; i++) {
            mn = fminf(mn, fminf(fminf(rv[i].x, rv[i].y), fminf(rv[i].z, rv[i].w)));
            mx = fmaxf(mx, fmaxf(fmaxf(rv[i].x, rv[i].y), fmaxf(rv[i].z, rv[i].w)));
        }
#pragma unroll
        for (int o = 16; o > 0; o >>= 1) {
            mn = fminf(mn, __shfl_xor_sync(0xFFFFFFFFu, mn, o));
            mx = fmaxf(mx, __shfl_xor_sync(0xFFFFFFFFu, mx, o));
        }
        if (l == 0) { s_red[w] = mn; s_red[NW + w] = mx; }
        __syncthreads();                               // JOIN A
        {
            float a = s_red[l & 7];
            float b = s_red[NW + (l & 7)];
#pragma unroll
            for (int o = 4; o > 0; o >>= 1) {
                a = fminf(a, __shfl_xor_sync(0xFFFFFFFFu, a, o));
                b = fmaxf(b, __shfl_xor_sync(0xFFFFFFFFu, b, o));
            }
            mn = a; mx = b;
        }
        const float width = mx - mn;
        const float scale = 128.0f / (width == 0.0f ? 1.0f : width);  // matches jnp where()
        const float nb = -mn * scale;

        // ---- Zero own warp hist: 8 STS.128, lanes spread across banks ----
        {
            uint4* hz = (uint4*)(s_hist + (w << 12));
            uint4 z = make_uint4(0u, 0u, 0u, 0u);
#pragma unroll
            for (int k = 0; k < 8; k++) hz[k * 32 + l] = z;
        }
        __syncwarp();

        // ---- Bin 64 values (warp-local, bank-CF byte RMW); NO LDGs here ----
        unsigned char* hb = s_hist + (w << 12) + (l << 2);
#pragma unroll
        for (int i = 0; i < 16; i++) {
            const float4 v = rv[i];
            const int b0 = (int)fminf(fmaf(v.x, scale, nb), 127.0f);
            const int b1 = (int)fminf(fmaf(v.y, scale, nb), 127.0f);
            const int b2 = (int)fminf(fmaf(v.z, scale, nb), 127.0f);
            const int b3 = (int)fminf(fmaf(v.w, scale, nb), 127.0f);
            // byte offset: (b>>2)*128 + (b&3) = ((b & 124) << 5) + (b & 3)
            const int o0 = ((b0 & 124) << 5) + (b0 & 3);
            const int o1 = ((b1 & 124) << 5) + (b1 & 3);
            const int o2 = ((b2 & 124) << 5) + (b2 & 3);
            const int o3 = ((b3 & 124) << 5) + (b3 & 3);
            const unsigned int e02 = (b2 == b0) ? 1u : 0u;
            const unsigned int e13 = (b3 == b1) ? 1u : 0u;
            // wave 1: loads of b0,b2 concurrent -> merged if equal
            unsigned int c0 = hb[o0];
            unsigned int c2 = hb[o2];
            hb[o0] = (unsigned char)(c0 + 1u + e02);
            if (!e02) hb[o2] = (unsigned char)(c2 + 1u);
            // wave 2: loads of b1,b3 after wave-1 stores (char aliasing)
            unsigned int c1 = hb[o1];
            unsigned int c3 = hb[o3];
            hb[o1] = (unsigned char)(c1 + 1u + e13);
            if (!e13) hb[o3] = (unsigned char)(c3 + 1u);
        }

        // ---- Prefetch burst for row r+GRID_P: 16 LDG.128, issued NOW so
        // DRAM transfers overlap the reduce/combine/epilogue tail ----
        if (has_next) {
#pragma unroll
            for (int i = 0; i < 16; i++) rv[i] = __ldcs(nxt + tid + i * NT);
        }
        __syncwarp();

        // ---- Warp-local reduce: lane l owns bins 4l..4l+3 (word row l).
        // Rotated reads: word l*32 + (j+l)&31 -> bank (j+l)&31, CF.
        // Packed u16 fields: max 32 words * 64 = 2048 < 65536.
        {
            const unsigned int* h32 = (const unsigned int*)(s_hist + (w << 12));
            unsigned int lo = 0u, hi = 0u;
#pragma unroll
            for (int j = 0; j < 32; j++) {
                unsigned int v32 = h32[(l << 5) + ((j + l) & 31)];
                lo += v32 & 0x00FF00FFu;
                hi += (v32 >> 8) & 0x00FF00FFu;
            }
            const int b4 = l << 2;
            s_pcnt[(b4 + 0) * 9 + w] = (int)(lo & 0xFFFFu);
            s_pcnt[(b4 + 1) * 9 + w] = (int)(hi & 0xFFFFu);
            s_pcnt[(b4 + 2) * 9 + w] = (int)(lo >> 16);
            s_pcnt[(b4 + 3) * 9 + w] = (int)(hi >> 16);
        }
        __syncthreads();                               // JOIN B

        // ---- Combine the 8 warps' partials (stride 9 -> CF banks) ----
        if (tid < N_BINS) {
            const int base = tid * 9;
            int s = 0;
#pragma unroll
            for (int w2 = 0; w2 < NW; w2++) s += s_pcnt[base + w2];
            s_cnt[tid] = (float)s;
        }
        __syncthreads();                               // JOIN B2

        // ---- Epilogue: out[row][o] = cnt.Wt/F + mn*S0 + wd*S1 + b.
        // s_cnt read as float4 broadcast: 8 LDS.128 instead of 32 LDS.32.
        {
            const int o = tid & 63;
            const int q = tid >> 6;                    // 4 chunks of 32 bins
            const float* wt = g_wt + (q * 32) * N_OUT + o;
            const float4* c4 = (const float4*)s_cnt + q * 8;
            float acc = 0.0f;
#pragma unroll
            for (int jj = 0; jj < 8; jj++) {
                const float4 cv = c4[jj];              // broadcast, 1 wf
                acc = fmaf(cv.x, __ldg(wt + (jj * 4 + 0) * N_OUT), acc);
                acc = fmaf(cv.y, __ldg(wt + (jj * 4 + 1) * N_OUT), acc);
                acc = fmaf(cv.z, __ldg(wt + (jj * 4 + 2) * N_OUT), acc);
                acc = fmaf(cv.w, __ldg(wt + (jj * 4 + 3) * N_OUT), acc);
            }
            s_part[tid] = acc;
        }
        __syncthreads();                               // JOIN C
        if (tid < 64) {
            const float bo = bias[tid];
            float s = (s_part[tid] + s_part[tid + 64]) +
                      (s_part[tid + 128] + s_part[tid + 192]);
            float res = fmaf(s, 1.0f / 16384.0f,
                             fmaf(mn, g_s0[tid], fmaf(width, g_s1[tid], bo)));
            out[(size_t)row * N_OUT + tid] = res;
        }

        if (!has_next) break;
        row = next;
    }
}

// ---------------------------------------------------------------------------
extern "C" void kernel_launch(void* const* d_in, const int* in_sizes, int n_in,
                              void* d_out, int out_size) {
    const float* x = (const float*)d_in[0];
    const float* W = (const float*)d_in[1];
    const float* b = (const float*)d_in[2];
    float* out = (float*)d_out;

    prep_kernel<<<N_OUT, 128>>>(W);
    hist_kernel<<<GRID_P, NT>>>(x, b, out);
}